// round 14
// baseline (speedup 1.0000x reference)
#include <cuda_runtime.h>

#define B_   256
#define C_   3
#define H_   224
#define W_   224
#define HW_  (H_ * W_)          // 50176
#define HW4  (HW_ / 4)          // 12544 float4 per plane
#define NSL  49                 // slices per image (CTAs in x)

#define GW0 0.2989f
#define GW1 0.587f
#define GW2 0.114f

// Deterministic scratch. g_cnt is MONOTONIC across graph replays: each CTA
// derives its epoch target from the atomicAdd return value, so no reset
// kernel is needed (replays are serialized by the harness).
__device__ float g_part[B_ * NSL * 3];
__device__ int   g_cnt[B_];

// ---------------------------------------------------------------------------
// Single fused kernel. Each CTA handles one (image, slice): loads its slice
// once (registers), contributes per-channel partial sums, then:
//  - non-contrast image: finalize clip(aug(x)*br) and exit (no waiting).
//  - contrast image: tid0 spins until all 49 slices of the image posted,
//    cooperative deterministic mean reduction, full affine transform, store.
// Input is read exactly once; total DRAM traffic = 154R + 154W = 308 MB.
// ---------------------------------------------------------------------------
__global__ __launch_bounds__(256) void fused_aug_kernel(
    const float* __restrict__ x,
    const float* __restrict__ brightness,
    const float* __restrict__ contrast_factor,
    const int*   __restrict__ flip_mask,
    const int*   __restrict__ gray_mask,
    const int*   __restrict__ contrast_apply,
    float*       __restrict__ out)
{
    const int b   = blockIdx.y;
    const int sl  = blockIdx.x;
    const int tid = threadIdx.x;
    const int p   = sl * 256 + tid;                      // < HW4 (49*256)

    const float br   = brightness[b];
    const bool  flip = flip_mask[b] != 0;
    const bool  gray = gray_mask[b] != 0;
    const bool  ctr  = contrast_apply[b] != 0;
    const float cf   = ctr ? contrast_factor[b] : 1.0f;

    // flip-aware source (sum is flip-invariant)
    const int pix = p * 4;
    const int h   = pix / W_;
    const int w   = pix - h * W_;
    const int sp4 = flip ? ((h * W_ + (W_ - 4 - w)) >> 2) : p;

    const float4* __restrict__ in4 =
        reinterpret_cast<const float4*>(x) + (size_t)b * 3 * HW4;
    float4 v0 = __ldcs(&in4[0 * HW4 + sp4]);             // read once, evict-first
    float4 v1 = __ldcs(&in4[1 * HW4 + sp4]);
    float4 v2 = __ldcs(&in4[2 * HW4 + sp4]);

    // ---- per-channel partial sums of ORIGINAL x ----
    float s0 = (v0.x + v0.y) + (v0.z + v0.w);
    float s1 = (v1.x + v1.y) + (v1.z + v1.w);
    float s2 = (v2.x + v2.y) + (v2.z + v2.w);
    #pragma unroll
    for (int o = 16; o; o >>= 1) {
        s0 += __shfl_xor_sync(~0u, s0, o);
        s1 += __shfl_xor_sync(~0u, s1, o);
        s2 += __shfl_xor_sync(~0u, s2, o);
    }
    __shared__ float red[3][8];
    if ((tid & 31) == 0) {
        red[0][tid >> 5] = s0; red[1][tid >> 5] = s1; red[2][tid >> 5] = s2;
    }
    __syncthreads();

    // ---- post partials, increment arrival counter, (contrast) spin ----
    if (tid == 0) {
        float a0 = 0.f, a1 = 0.f, a2 = 0.f;
        #pragma unroll
        for (int q = 0; q < 8; q++) { a0 += red[0][q]; a1 += red[1][q]; a2 += red[2][q]; }
        const int off = (b * NSL + sl) * 3;
        g_part[off + 0] = a0; g_part[off + 1] = a1; g_part[off + 2] = a2;
        __threadfence();                                 // partials before count
        const int old    = atomicAdd(&g_cnt[b], 1);
        const int target = old - (old % NSL) + NSL;      // end of THIS epoch
        if (ctr) {
            volatile int* c = &g_cnt[b];
            while (*c < target) __nanosleep(64);
        }
    }
    __syncthreads();

    float4* __restrict__ out4 =
        reinterpret_cast<float4*>(out) + (size_t)b * 3 * HW4;

    if (!ctr) {
        // ---- no-contrast: out = clip(aug(x)*br), done ----
        if (flip) {
            float t;
            t = v0.x; v0.x = v0.w; v0.w = t;  t = v0.y; v0.y = v0.z; v0.z = t;
            t = v1.x; v1.x = v1.w; v1.w = t;  t = v1.y; v1.y = v1.z; v1.z = t;
            t = v2.x; v2.x = v2.w; v2.w = t;  t = v2.y; v2.y = v2.z; v2.z = t;
        }
        if (gray) {
            float4 g;
            g.x = GW0*v0.x + GW1*v1.x + GW2*v2.x;
            g.y = GW0*v0.y + GW1*v1.y + GW2*v2.y;
            g.z = GW0*v0.z + GW1*v1.z + GW2*v2.z;
            g.w = GW0*v0.w + GW1*v1.w + GW2*v2.w;
            v0 = g; v1 = g; v2 = g;
        }
        #define XFB(v)                                                       \
            v.x = fminf(fmaxf(v.x * br, -2.5f), 2.5f);                       \
            v.y = fminf(fmaxf(v.y * br, -2.5f), 2.5f);                       \
            v.z = fminf(fmaxf(v.z * br, -2.5f), 2.5f);                       \
            v.w = fminf(fmaxf(v.w * br, -2.5f), 2.5f);
        XFB(v0) XFB(v1) XFB(v2)
        #undef XFB
        __stcs(&out4[0 * HW4 + p], v0);
        __stcs(&out4[1 * HW4 + p], v1);
        __stcs(&out4[2 * HW4 + p], v2);
        return;
    }

    // ---- contrast path: cooperative deterministic mean reduction ----
    __shared__ float sm_mean[3];
    if (tid < 96) {
        const int c    = tid >> 5;
        const int lane = tid & 31;
        float s = 0.f;
        if (lane < NSL)      s  = __ldcg(&g_part[(b * NSL + lane) * 3 + c]);
        if (lane + 32 < NSL) s += __ldcg(&g_part[(b * NSL + lane + 32) * 3 + c]);
        #pragma unroll
        for (int o = 16; o; o >>= 1)
            s += __shfl_xor_sync(~0u, s, o);
        if (lane == 0)
            sm_mean[c] = s * (1.0f / (float)HW_);
    }
    __syncthreads();

    const float m0 = sm_mean[0];
    const float m1 = sm_mean[1];
    const float m2 = sm_mean[2];
    const float gm = GW0 * m0 + GW1 * m1 + GW2 * m2;

    const float mm0 = (gray ? gm : m0) * br;
    const float mm1 = (gray ? gm : m1) * br;
    const float mm2 = (gray ? gm : m2) * br;

    const float scale = br * cf;
    const float omcf  = 1.0f - cf;
    const float off0 = mm0 * omcf;
    const float off1 = mm1 * omcf;
    const float off2 = mm2 * omcf;

    if (flip) {
        float t;
        t = v0.x; v0.x = v0.w; v0.w = t;  t = v0.y; v0.y = v0.z; v0.z = t;
        t = v1.x; v1.x = v1.w; v1.w = t;  t = v1.y; v1.y = v1.z; v1.z = t;
        t = v2.x; v2.x = v2.w; v2.w = t;  t = v2.y; v2.y = v2.z; v2.z = t;
    }
    if (gray) {
        float4 g;
        g.x = GW0*v0.x + GW1*v1.x + GW2*v2.x;
        g.y = GW0*v0.y + GW1*v1.y + GW2*v2.y;
        g.z = GW0*v0.z + GW1*v1.z + GW2*v2.z;
        g.w = GW0*v0.w + GW1*v1.w + GW2*v2.w;
        v0 = g; v1 = g; v2 = g;
    }

    #define XFORM(v, off)                                                    \
        v.x = fminf(fmaxf(fmaf(v.x, scale, off), -2.5f), 2.5f);             \
        v.y = fminf(fmaxf(fmaf(v.y, scale, off), -2.5f), 2.5f);             \
        v.z = fminf(fmaxf(fmaf(v.z, scale, off), -2.5f), 2.5f);             \
        v.w = fminf(fmaxf(fmaf(v.w, scale, off), -2.5f), 2.5f);
    XFORM(v0, off0)
    XFORM(v1, off1)
    XFORM(v2, off2)
    #undef XFORM

    __stcs(&out4[0 * HW4 + p], v0);
    __stcs(&out4[1 * HW4 + p], v1);
    __stcs(&out4[2 * HW4 + p], v2);
}

extern "C" void kernel_launch(void* const* d_in, const int* in_sizes, int n_in,
                              void* d_out, int out_size) {
    const float* x   = (const float*)d_in[0];
    const float* br  = (const float*)d_in[1];
    const float* cfv = (const float*)d_in[2];
    const int*   fm  = (const int*)d_in[3];
    const int*   gm  = (const int*)d_in[4];
    const int*   ca  = (const int*)d_in[5];
    float* out = (float*)d_out;

    dim3 grid(NSL, B_);                                  // (49, 256)
    fused_aug_kernel<<<grid, 256>>>(x, br, cfv, fm, gm, ca, out);
}